// round 11
// baseline (speedup 1.0000x reference)
#include <cuda_runtime.h>
#include <math.h>

#define B_SAMPLES 128
#define T_LEN     8192
#define C_CLASSES 64
#define OUT_LEN   8

#define THREADS   256
#define CTAS_PER_SAMPLE 128                 // 64 positions per CTA
#define EPT2      32                        // topk elems per thread (8192/256)
#define L2E       1.4426950408889634f

// Scratch (allocation-free __device__ globals; g_cnt zero-init, consumer-reset)
__device__ __align__(16) float         g_conf[B_SAMPLES * T_LEN];
__device__ __align__(16) unsigned char g_pred[B_SAMPLES * T_LEN];
__device__ int g_cnt[B_SAMPLES];

__device__ __forceinline__ float ex2_approx(float t) {
    float r;
    asm("ex2.approx.ftz.f32 %0, %1;" : "=f"(r) : "f"(t));
    return r;
}

// ---------------------------------------------------------------------------
// Fused: full-chip streaming grid + last-CTA-per-sample top-k epilogue.
// ---------------------------------------------------------------------------
__global__ __launch_bounds__(THREADS, 6)
void fused_kernel(const float* __restrict__ x, float* __restrict__ out) {
    __shared__ unsigned char spred[T_LEN];          // 8 KB (epilogue only)
    __shared__ float candv[OUT_LEN * 8];
    __shared__ int   candi[OUT_LEN * 8];
    __shared__ float outv[OUT_LEN];
    __shared__ int   outi[OUT_LEN];
    __shared__ int   s_last;

    const int tid = threadIdx.x;
    const int b   = blockIdx.x >> 7;               // 128 CTAs per sample

    // ================= Streaming: 64 positions, 4 threads/position ==========
    {
        const int part = tid & 3;
        const size_t pos = (size_t)blockIdx.x * 64 + (tid >> 2);
        const float4* __restrict__ p =
            (const float4*)(x + pos * C_CLASSES + part * 16);
        float4 v0 = p[0], v1 = p[1], v2 = p[2], v3 = p[3];

        float r[16] = {v0.x, v0.y, v0.z, v0.w, v1.x, v1.y, v1.z, v1.w,
                       v2.x, v2.y, v2.z, v2.w, v3.x, v3.y, v3.z, v3.w};

        float m = r[0];
        #pragma unroll
        for (int c = 1; c < 16; c++) m = fmaxf(m, r[c]);

        int am = 0;                                  // first-occurrence argmax
        #pragma unroll
        for (int c = 15; c >= 0; c--)
            if (r[c] >= m) am = c;
        int amg = part * 16 + am;

        #pragma unroll
        for (int d = 1; d < 4; d <<= 1) {
            float om = __shfl_xor_sync(0xFFFFFFFFu, m,   d);
            int   oa = __shfl_xor_sync(0xFFFFFFFFu, amg, d);
            if (om > m || (om == m && oa < amg)) { m = om; amg = oa; }
        }

        float mb = m * L2E;
        float s = 0.0f;
        #pragma unroll
        for (int c = 0; c < 16; c++)
            s += ex2_approx(fmaf(r[c], L2E, -mb));
        #pragma unroll
        for (int d = 1; d < 4; d <<= 1)
            s += __shfl_xor_sync(0xFFFFFFFFu, s, d);

        if (part == 0) {
            g_conf[pos] = __fdividef(1.0f, s);
            g_pred[pos] = (unsigned char)amg;
        }
    }

    // ================= Last-CTA ticket ======================================
    __syncthreads();
    if (tid == 0) {
        __threadfence();                             // publish conf/pred
        int t = atomicAdd(&g_cnt[b], 1);
        int last = (t == CTAS_PER_SAMPLE - 1);
        if (last) g_cnt[b] = 0;                      // reset for next replay
        s_last = last;
    }
    __syncthreads();
    if (!s_last) return;
    __threadfence();                                 // acquire

    // ================= Epilogue: RLE + top-8 for sample b (256 thr) =========
    const size_t off = (size_t)b * T_LEN;
    const int t0   = tid * EPT2;
    const int lane = tid & 31;
    const int wid  = tid >> 5;

    // Front-batched loads (L2-hot: just written by this sample's CTAs)
    uint4 P0 = ((const uint4*)(g_pred + off))[tid * 2];
    uint4 P1 = ((const uint4*)(g_pred + off))[tid * 2 + 1];
    float4 C[8];
    #pragma unroll
    for (int i = 0; i < 8; i++)
        C[i] = ((const float4*)(g_conf + off))[tid * 8 + i];

    ((uint4*)spred)[tid * 2]     = P0;
    ((uint4*)spred)[tid * 2 + 1] = P1;
    __syncthreads();

    unsigned u[8] = {P0.x, P0.y, P0.z, P0.w, P1.x, P1.y, P1.z, P1.w};
    float cf[EPT2];
    #pragma unroll
    for (int i = 0; i < 8; i++) {
        cf[4*i]   = C[i].x; cf[4*i+1] = C[i].y;
        cf[4*i+2] = C[i].z; cf[4*i+3] = C[i].w;
    }

    unsigned char prev = (tid == 0)
        ? (unsigned char)((u[0] & 0xFFu) ^ 1u) : spred[t0 - 1];

    float lv[EPT2];
    #pragma unroll
    for (int j = 0; j < EPT2; j++) {
        unsigned char cur = (unsigned char)((u[j >> 2] >> ((j & 3) * 8)) & 0xFFu);
        unsigned char before = (j == 0) ? prev
            : (unsigned char)((u[(j-1) >> 2] >> (((j-1) & 3) * 8)) & 0xFFu);
        bool start = (t0 + j == 0) || (cur != before);
        float v = -INFINITY;
        if (start) {
            int cnt = 1;
            int e = t0 + j + 1;
            while (e < T_LEN && spred[e] == cur) { cnt++; e++; }  // ~1 iter avg
            v = cf[j] * (float)cnt;
        }
        lv[j] = v;
    }

    // ---- Phase A: per-warp top-8 (mask-consume, static indexing only) ----
    unsigned mask = 0;
    float bv = -INFINITY; int bj = 0;
    #pragma unroll
    for (int j = 0; j < EPT2; j++)
        if (lv[j] > bv) { bv = lv[j]; bj = j; }      // j asc -> first-max tie

    for (int k = 0; k < OUT_LEN; k++) {
        float wv = bv; int wi = t0 + bj;
        #pragma unroll
        for (int d = 16; d > 0; d >>= 1) {
            float ov = __shfl_xor_sync(0xFFFFFFFFu, wv, d);
            int   oi = __shfl_xor_sync(0xFFFFFFFFu, wi, d);
            if (ov > wv || (ov == wv && oi < wi)) { wv = ov; wi = oi; }
        }
        if (lane == 0) { candv[k * 8 + wid] = wv; candi[k * 8 + wid] = wi; }
        if ((wi >> 5) == tid) {                      // owner consumes + rescan
            mask |= 1u << (wi & 31);
            bv = -INFINITY; bj = 0;
            #pragma unroll
            for (int j = 0; j < EPT2; j++)
                if (!(mask & (1u << j)) && lv[j] > bv) { bv = lv[j]; bj = j; }
        }
    }
    __syncthreads();

    // ---- Phase B: warp 0 merges 8x8 candidates ----
    if (wid == 0) {
        float cv[OUT_LEN]; int ci[OUT_LEN];
        #pragma unroll
        for (int r = 0; r < OUT_LEN; r++) {
            if (lane < 8) { cv[r] = candv[r * 8 + lane]; ci[r] = candi[r * 8 + lane]; }
            else          { cv[r] = -INFINITY;           ci[r] = 0x7FFFFFFF; }
        }
        // Per-lane lists are value-desc / index-asc on ties: strict > keeps
        // the lowest-index tie, matching lax.top_k.
        unsigned m2 = 0;
        float bv2 = -INFINITY; int bi2 = 0x7FFFFFFF, br2 = 0;
        #pragma unroll
        for (int r = 0; r < OUT_LEN; r++)
            if (cv[r] > bv2) { bv2 = cv[r]; bi2 = ci[r]; br2 = r; }

        for (int k = 0; k < OUT_LEN; k++) {
            float wv = bv2; int wi = bi2;
            #pragma unroll
            for (int d = 16; d > 0; d >>= 1) {
                float ov = __shfl_xor_sync(0xFFFFFFFFu, wv, d);
                int   oi = __shfl_xor_sync(0xFFFFFFFFu, wi, d);
                if (ov > wv || (ov == wv && oi < wi)) { wv = ov; wi = oi; }
            }
            if (lane == 0) { outv[k] = wv; outi[k] = wi; }
            if (bv2 == wv && bi2 == wi) {            // owner (unique real idx)
                m2 |= 1u << br2;
                bv2 = -INFINITY; bi2 = 0x7FFFFFFF; br2 = 0;
                #pragma unroll
                for (int r = 0; r < OUT_LEN; r++)
                    if (!(m2 & (1u << r)) && cv[r] > bv2) {
                        bv2 = cv[r]; bi2 = ci[r]; br2 = r;
                    }
            }
        }
    }
    __syncthreads();

    if (tid < OUT_LEN) {
        float v = outv[tid];
        int   i = outi[tid];
        float o = 0.0f;                              // pad-with-zero path
        if (isfinite(v)) o = (float)spred[i];
        out[(size_t)b * OUT_LEN + tid] = o;
    }
}

// ---------------------------------------------------------------------------
extern "C" void kernel_launch(void* const* d_in, const int* in_sizes, int n_in,
                              void* d_out, int out_size) {
    const float* x = (const float*)d_in[0];
    float* out = (float*)d_out;

    fused_kernel<<<B_SAMPLES * CTAS_PER_SAMPLE, THREADS>>>(x, out);
}

// round 12
// speedup vs baseline: 1.3180x; 1.3180x over previous
#include <cuda_runtime.h>
#include <math.h>

#define B_SAMPLES 128
#define T_LEN     8192
#define C_CLASSES 64
#define OUT_LEN   8

#define K1_THREADS 256
#define POS_PER_CTA (K1_THREADS / 4)            // 4 threads per position
#define L2E 1.4426950408889634f

#define CHUNKS    4                              // K2 CTAs per sample
#define CHUNK_LEN (T_LEN / CHUNKS)               // 2048
#define K2_THREADS 256
#define EPT 8                                    // contiguous elems per thread

// Scratch (allocation-free __device__ globals)
__device__ __align__(16) float         g_conf[B_SAMPLES * T_LEN];
__device__ __align__(16) unsigned char g_pred[B_SAMPLES * T_LEN];
__device__ __align__(16) float g_candv[B_SAMPLES * CHUNKS * OUT_LEN];
__device__ __align__(16) int   g_candi[B_SAMPLES * CHUNKS * OUT_LEN];

__device__ __forceinline__ float ex2_approx(float t) {
    float r;
    asm("ex2.approx.ftz.f32 %0, %1;" : "=f"(r) : "f"(t));
    return r;
}

// ---------------------------------------------------------------------------
// K1: softmax confidence (max prob) + argmax — UNCHANGED from R10 (40us,
// ~6.4 TB/s = LTS cap). Do not touch.
// ---------------------------------------------------------------------------
__global__ __launch_bounds__(K1_THREADS)
void softmax_conf_kernel(const float* __restrict__ x) {
    const int tid  = threadIdx.x;
    const int part = tid & 3;
    const size_t pos = (size_t)blockIdx.x * POS_PER_CTA + (tid >> 2);

    const float4* __restrict__ p =
        (const float4*)(x + pos * C_CLASSES + part * 16);
    float4 v0 = p[0], v1 = p[1], v2 = p[2], v3 = p[3];

    float r[16] = {v0.x, v0.y, v0.z, v0.w, v1.x, v1.y, v1.z, v1.w,
                   v2.x, v2.y, v2.z, v2.w, v3.x, v3.y, v3.z, v3.w};

    float m = r[0];
    #pragma unroll
    for (int c = 1; c < 16; c++) m = fmaxf(m, r[c]);

    int am = 0;                                   // first-occurrence argmax
    #pragma unroll
    for (int c = 15; c >= 0; c--)
        if (r[c] >= m) am = c;
    int amg = part * 16 + am;

    #pragma unroll
    for (int d = 1; d < 4; d <<= 1) {
        float om = __shfl_xor_sync(0xFFFFFFFFu, m,   d);
        int   oa = __shfl_xor_sync(0xFFFFFFFFu, amg, d);
        if (om > m || (om == m && oa < amg)) { m = om; amg = oa; }
    }

    float mb = m * L2E;
    float s = 0.0f;
    #pragma unroll
    for (int c = 0; c < 16; c++)
        s += ex2_approx(fmaf(r[c], L2E, -mb));
    #pragma unroll
    for (int d = 1; d < 4; d <<= 1)
        s += __shfl_xor_sync(0xFFFFFFFFu, s, d);

    if (part == 0) {
        g_conf[pos] = __fdividef(1.0f, s);
        g_pred[pos] = (unsigned char)amg;
    }
}

// ---------------------------------------------------------------------------
// K2: per-chunk RLE + top-8 candidates. 4 CTAs x 256 thr per sample.
// ---------------------------------------------------------------------------
__global__ __launch_bounds__(K2_THREADS)
void chunk_topk_kernel() {
    __shared__ unsigned char spred[CHUNK_LEN];       // 2 KB
    __shared__ float candv[OUT_LEN * 8];             // [round][warp]
    __shared__ int   candi[OUT_LEN * 8];

    const int b     = blockIdx.x >> 2;
    const int chunk = blockIdx.x & 3;
    const int tid   = threadIdx.x;
    const int lane  = tid & 31;
    const int wid   = tid >> 5;

    const size_t coff = (size_t)b * T_LEN + chunk * CHUNK_LEN;  // chunk base
    const int tloc = tid * EPT;                       // local [0,2048)
    const int gt0  = (int)(chunk * CHUNK_LEN) + tloc; // sample-local index

    // ---- Front-batched unconditional loads ----
    uint2  pv2 = ((const uint2*)(g_pred + coff))[tid];
    float4 c0  = ((const float4*)(g_conf + coff))[tid * 2];
    float4 c1  = ((const float4*)(g_conf + coff))[tid * 2 + 1];
    // previous pred byte (cross-chunk boundary via global)
    unsigned char prev = 0;
    if (tloc == 0 && gt0 > 0) prev = g_pred[coff - 1];

    ((uint2*)spred)[tid] = pv2;
    __syncthreads();

    unsigned char pb[EPT];
    pb[0] = (unsigned char)(pv2.x);        pb[1] = (unsigned char)(pv2.x >> 8);
    pb[2] = (unsigned char)(pv2.x >> 16);  pb[3] = (unsigned char)(pv2.x >> 24);
    pb[4] = (unsigned char)(pv2.y);        pb[5] = (unsigned char)(pv2.y >> 8);
    pb[6] = (unsigned char)(pv2.y >> 16);  pb[7] = (unsigned char)(pv2.y >> 24);
    float cf[EPT] = {c0.x, c0.y, c0.z, c0.w, c1.x, c1.y, c1.z, c1.w};

    if (tloc > 0) prev = spred[tloc - 1];
    else if (gt0 == 0) prev = (unsigned char)(pb[0] ^ 1);  // t==0 always starts

    float lv[EPT];
    #pragma unroll
    for (int j = 0; j < EPT; j++) {
        unsigned char cur = pb[j];
        unsigned char before = (j == 0) ? prev : pb[j - 1];
        float v = -INFINITY;
        if (cur != before || (gt0 + j == 0)) {
            int cnt = 1;
            int jj = j + 1;
            while (jj < EPT && pb[jj] == cur) { cnt++; jj++; }   // reg scan
            if (jj == EPT) {                                      // smem scan
                int e = tloc + EPT;
                while (e < CHUNK_LEN && spred[e] == cur) { cnt++; e++; }
                if (e == CHUNK_LEN) {                             // global tail
                    size_t ge = coff + CHUNK_LEN;
                    size_t gend = (size_t)b * T_LEN + T_LEN;
                    while (ge < gend && g_pred[ge] == cur) { cnt++; ge++; }
                }
            }
            v = cf[j] * (float)cnt;
        }
        lv[j] = v;
    }

    // ---- Phase A: per-warp top-8 ----
    #pragma unroll
    for (int k = 0; k < OUT_LEN; k++) {
        float bv = lv[0];
        int   bj = 0;
        #pragma unroll
        for (int j = 1; j < EPT; j++)
            if (lv[j] > bv) { bv = lv[j]; bj = j; }   // j asc = idx asc
        int bi = gt0 + bj;                            // sample-local index

        #pragma unroll
        for (int d = 16; d > 0; d >>= 1) {
            float ov = __shfl_xor_sync(0xFFFFFFFFu, bv, d);
            int   oi = __shfl_xor_sync(0xFFFFFFFFu, bi, d);
            if (ov > bv || (ov == bv && oi < bi)) { bv = ov; bi = oi; }
        }
        if (lane == 0) { candv[k * 8 + wid] = bv; candi[k * 8 + wid] = bi; }
        if (((bi - chunk * CHUNK_LEN) >> 3) == tid)   // owner invalidates
            lv[bi & (EPT - 1)] = -INFINITY;
    }
    __syncthreads();

    // ---- Phase B: warp 0 merges 8x8 -> chunk finalists ----
    if (wid == 0) {
        float cv[OUT_LEN]; int ci[OUT_LEN];
        #pragma unroll
        for (int r = 0; r < OUT_LEN; r++) {
            if (lane < 8) { cv[r] = candv[r * 8 + lane]; ci[r] = candi[r * 8 + lane]; }
            else          { cv[r] = -INFINITY;           ci[r] = 0x7FFFFFFF; }
        }
        #pragma unroll
        for (int k = 0; k < OUT_LEN; k++) {
            float bv = cv[0];
            int   bi = ci[0], br = 0;
            #pragma unroll
            for (int r = 1; r < OUT_LEN; r++)
                if (cv[r] > bv) { bv = cv[r]; bi = ci[r]; br = r; }
            float mv = bv; int mi = bi;
            #pragma unroll
            for (int d = 16; d > 0; d >>= 1) {
                float ov = __shfl_xor_sync(0xFFFFFFFFu, mv, d);
                int   oi = __shfl_xor_sync(0xFFFFFFFFu, mi, d);
                if (ov > mv || (ov == mv && oi < mi)) { mv = ov; mi = oi; }
            }
            if (lane == 0) {
                int slot = (b * CHUNKS + chunk) * OUT_LEN + k;
                g_candv[slot] = mv;
                g_candi[slot] = isinf(mv) ? 0x7FFFFFFF : mi;
            }
            if (bv == mv && bi == mi) {               // owner consumes
                cv[br] = -INFINITY; ci[br] = 0x7FFFFFFF;
            }
        }
    }
}

// ---------------------------------------------------------------------------
// K3: merge 4x8 candidates per sample -> output. 128 CTAs x 32 threads.
// ---------------------------------------------------------------------------
__global__ __launch_bounds__(32)
void merge_kernel(float* __restrict__ out) {
    const int b    = blockIdx.x;
    const int lane = threadIdx.x;

    float v = g_candv[b * 32 + lane];                 // 32 candidates/sample
    int   i = g_candi[b * 32 + lane];

    float resv[OUT_LEN]; int resi[OUT_LEN];
    #pragma unroll
    for (int k = 0; k < OUT_LEN; k++) {
        float wv = v; int wi = i;
        #pragma unroll
        for (int d = 16; d > 0; d >>= 1) {
            float ov = __shfl_xor_sync(0xFFFFFFFFu, wv, d);
            int   oi = __shfl_xor_sync(0xFFFFFFFFu, wi, d);
            if (ov > wv || (ov == wv && oi < wi)) { wv = ov; wi = oi; }
        }
        resv[k] = wv; resi[k] = wi;
        if (v == wv && i == wi) { v = -INFINITY; i = 0x7FFFFFFF; }
    }

    if (lane < OUT_LEN) {
        float rv = resv[lane];
        int   ri = resi[lane];
        float o = 0.0f;                               // pad-with-zero path
        if (isfinite(rv)) o = (float)g_pred[(size_t)b * T_LEN + ri];
        out[(size_t)b * OUT_LEN + lane] = o;
    }
}

// ---------------------------------------------------------------------------
extern "C" void kernel_launch(void* const* d_in, const int* in_sizes, int n_in,
                              void* d_out, int out_size) {
    const float* x = (const float*)d_in[0];
    float* out = (float*)d_out;

    const int n_pos = B_SAMPLES * T_LEN;
    softmax_conf_kernel<<<n_pos / POS_PER_CTA, K1_THREADS>>>(x);
    chunk_topk_kernel<<<B_SAMPLES * CHUNKS, K2_THREADS>>>();
    merge_kernel<<<B_SAMPLES, 32>>>(out);
}